// round 11
// baseline (speedup 1.0000x reference)
#include <cuda_runtime.h>
#include <cstdint>

// Problem constants
#define EDIM   127
#define BN     2048                 // B*N
#define BNE    260096               // B*N*E

#define CT      512
#define NODES   8
#define GROUPS  256                 // BN / NODES

// Static smem (floats)
#define H2PAD  132
#define AXPAD  65
#define V11PAD 49
#define VTPAD  36

#define OUT1_BASE4 1040384          // (BNE*16)/4

__device__ __forceinline__ float warp_sum(float v) {
    v += __shfl_xor_sync(0xffffffffu, v, 16);
    v += __shfl_xor_sync(0xffffffffu, v, 8);
    v += __shfl_xor_sync(0xffffffffu, v, 4);
    v += __shfl_xor_sync(0xffffffffu, v, 2);
    v += __shfl_xor_sync(0xffffffffu, v, 1);
    return v;
}

// packed fp32x2 FMA: d = a*b + d
__device__ __forceinline__ void ffma2(unsigned long long& d,
                                      unsigned long long a,
                                      unsigned long long b) {
    asm("fma.rn.f32x2 %0, %1, %2, %0;" : "+l"(d) : "l"(a), "l"(b));
}

// 8-float partial dot: w from global (L2), h in registers. Returns scalar sum.
__device__ __forceinline__ float dot8(const float* __restrict__ wrow,
                                      const ulonglong2& h01, const ulonglong2& h23)
{
    ulonglong2 wa = __ldg((const ulonglong2*)wrow);
    ulonglong2 wb = __ldg((const ulonglong2*)(wrow + 4));
    unsigned long long acA = 0ull, acB = 0ull;
    ffma2(acA, wa.x, h01.x);
    ffma2(acB, wa.y, h01.y);
    ffma2(acA, wb.x, h23.x);
    ffma2(acB, wb.y, h23.y);
    return (__uint_as_float((unsigned)acA) + __uint_as_float((unsigned)(acA >> 32)))
         + (__uint_as_float((unsigned)acB) + __uint_as_float((unsigned)(acB >> 32)));
}

extern "C" __global__ void __launch_bounds__(CT, 2)
fused_kernel(const float* __restrict__ r,
             const float* __restrict__ src0,
             const float* __restrict__ src1,
             const float* __restrict__ b00g,
             const float* __restrict__ b01g,
             const float* __restrict__ b10g,
             const float* __restrict__ b11g,
             const float* __restrict__ w1,
             const float* __restrict__ b1,
             const float* __restrict__ g1,
             const float* __restrict__ be1,
             const float* __restrict__ w2,
             const float* __restrict__ b2,
             const float* __restrict__ g2,
             const float* __restrict__ be2,
             const float* __restrict__ w300, const float* __restrict__ b300,
             const float* __restrict__ w301, const float* __restrict__ b301,
             const float* __restrict__ w310, const float* __restrict__ b310,
             const float* __restrict__ w311, const float* __restrict__ b311,
             float4* __restrict__ out)
{
    __shared__ float h2s[NODES * H2PAD];        // [node][m*32+k]
    __shared__ float axA[NODES * AXPAD];        // c00@0 s0@16 ws1@32 b01@48
    __shared__ float4 v4[NODES * V11PAD];       // v11: a in xyz
    __shared__ float vtmp[16 * VTPAD];          // per-warp layer1 output
    __shared__ float msg[NODES * 64];           // final messages

    const int t    = threadIdx.x;
    const int lane = t & 31;
    const int w    = t >> 5;           // 0..15
    const int blk  = blockIdx.x;

    // ---- prologue: warp w -> node (w&7), m-pair (w>>3) ----
    const int pnode = w & 7;
    const int mpair = w >> 3;
    const int node0 = blk * NODES + pnode;
    const int eb    = node0 * EDIM;
    const float x   = r[eb];
    const int k     = lane;

    #pragma unroll
    for (int mi = 0; mi < 2; mi++) {
        const int m = mpair * 2 + mi;
        // layer1 + LN + relu
        float v = fmaf(x, w1[m * 32 + k], b1[m * 32 + k]);
        float mu = warp_sum(v) * (1.f / 32.f);
        float d = v - mu;
        float var = warp_sum(d * d) * (1.f / 32.f);
        v = fmaf(d * rsqrtf(var + 1e-5f), g1[m * 32 + k], be1[m * 32 + k]);
        v = fmaxf(v, 0.f);
        vtmp[w * VTPAD + k] = v;
        __syncwarp();

        // layer2: stream w2 row k from L2, v from smem (broadcast)
        const float4* w2r4 = (const float4*)(w2 + (m * 32 + k) * 32);
        const float4* vt4  = (const float4*)(vtmp + w * VTPAD);
        float a0 = b2[m * 32 + k], a1 = 0.f;
        #pragma unroll
        for (int q = 0; q < 8; q += 2) {
            float4 wv0 = __ldg(&w2r4[q]);
            float4 vv0 = vt4[q];
            float4 wv1 = __ldg(&w2r4[q + 1]);
            float4 vv1 = vt4[q + 1];
            a0 = fmaf(wv0.x, vv0.x, a0); a0 = fmaf(wv0.y, vv0.y, a0);
            a0 = fmaf(wv0.z, vv0.z, a0); a0 = fmaf(wv0.w, vv0.w, a0);
            a1 = fmaf(wv1.x, vv1.x, a1); a1 = fmaf(wv1.y, vv1.y, a1);
            a1 = fmaf(wv1.z, vv1.z, a1); a1 = fmaf(wv1.w, vv1.w, a1);
        }
        float acc = a0 + a1;
        float mu2 = warp_sum(acc) * (1.f / 32.f);
        float d2 = acc - mu2;
        float var2 = warp_sum(d2 * d2) * (1.f / 32.f);
        acc = fmaf(d2 * rsqrtf(var2 + 1e-5f), g2[m * 32 + k], be2[m * 32 + k]);
        acc = fmaxf(acc, 0.f);
        h2s[pnode * H2PAD + m * 32 + k] = acc;
        __syncwarp();
    }

    // ---- per-node aux: warps 0-7 -> axA fields; warps 8-15 -> v11 ----
    if (lane < 16) {
        const int j = lane;
        if (w < 8) {
            float s0v = src0[eb * 16 + j];
            float s1a = src1[eb * 48 + j * 3 + 0];
            float s1b = src1[eb * 48 + j * 3 + 1];
            float s1c = src1[eb * 48 + j * 3 + 2];
            axA[pnode * AXPAD + j]      = b00g[node0] * s0v;          // c00
            axA[pnode * AXPAD + 16 + j] = s0v;                        // s0
            axA[pnode * AXPAD + 32 + j] = b10g[node0 * 3 + 0] * s1a   // ws1
                                        + b10g[node0 * 3 + 1] * s1b
                                        + b10g[node0 * 3 + 2] * s1c;
            if (j < 3) axA[pnode * AXPAD + 48 + j] = b01g[node0 * 3 + j];
        } else {
            float s1a = src1[eb * 48 + j * 3 + 0];
            float s1b = src1[eb * 48 + j * 3 + 1];
            float s1c = src1[eb * 48 + j * 3 + 2];
            #pragma unroll
            for (int f = 0; f < 3; f++) {
                float v0 = b11g[node0 * 27 + 0 + f] * s1a
                         + b11g[node0 * 27 + 3 + f] * s1b
                         + b11g[node0 * 27 + 6 + f] * s1c;
                float v1 = b11g[node0 * 27 + 9 + f] * s1a
                         + b11g[node0 * 27 + 12 + f] * s1b
                         + b11g[node0 * 27 + 15 + f] * s1c;
                float v2 = b11g[node0 * 27 + 18 + f] * s1a
                         + b11g[node0 * 27 + 21 + f] * s1b
                         + b11g[node0 * 27 + 24 + f] * s1c;
                v4[pnode * V11PAD + j * 3 + f] = make_float4(v0, v1, v2, 0.f);
            }
        }
    }
    __syncthreads();

    // ---- main loop: warp = out-channel i; lane = node*4 + kq (K/4 each) ----
    const int i    = w;
    const int node = lane >> 2;
    const int kq   = lane & 3;
    const int koff = kq * 8;

    const float* axn  = axA + node * AXPAD;
    const float4* v4n = v4 + node * V11PAD;
    const float b01r0 = axn[48], b01r1 = axn[49], b01r2 = axn[50];

    const float* hrow = h2s + node * H2PAD + koff;

    float z0 = 0.f, y0 = 0.f, y1 = 0.f, y2 = 0.f;
    ulonglong2 h01, h23;

#define LOAD_H(m) { const ulonglong2* hp = (const ulonglong2*)(hrow + (m) * 32); \
    h01 = hp[0]; h23 = hp[1]; }

    // ch0: w300, m0 -> msg0 via c00
    LOAD_H(0);
    {
        const float* wb = w300 + i * 512 + koff;
        const float* bb = b300 + i * 16;
        #pragma unroll 4
        for (int gq = 0; gq < 16; gq++) {
            float s = dot8(wb + gq * 32, h01, h23) + 0.25f * __ldg(bb + gq);
            z0 = fmaf(s, axn[gq], z0);
        }
    }
    // ch1: w301, m1 -> msg1 via s0 * b01[a]
    LOAD_H(1);
    {
        const float* wb = w301 + i * 512 + koff;
        const float* bb = b301 + i * 16;
        #pragma unroll 4
        for (int gq = 0; gq < 16; gq++) {
            float s = dot8(wb + gq * 32, h01, h23) + 0.25f * __ldg(bb + gq);
            float tt = s * axn[16 + gq];
            y0 = fmaf(tt, b01r0, y0);
            y1 = fmaf(tt, b01r1, y1);
            y2 = fmaf(tt, b01r2, y2);
        }
    }
    // ch2: w310, m2 -> msg0 via ws1
    LOAD_H(2);
    {
        const float* wb = w310 + i * 512 + koff;
        const float* bb = b310 + i * 16;
        #pragma unroll 4
        for (int gq = 0; gq < 16; gq++) {
            float s = dot8(wb + gq * 32, h01, h23) + 0.25f * __ldg(bb + gq);
            z0 = fmaf(s, axn[32 + gq], z0);
        }
    }
    // ch3..5: w311 rows i*48 + cc*16 + gq, m3 -> msg1 via v11
    LOAD_H(3);
    #pragma unroll 1
    for (int cc = 0; cc < 3; cc++) {
        const float* wb = w311 + (i * 48 + cc * 16) * 32 + koff;
        const float* bb = b311 + i * 48 + cc * 16;
        const float4* vv = v4n + cc * 16;
        #pragma unroll 4
        for (int gq = 0; gq < 16; gq++) {
            float s = dot8(wb + gq * 32, h01, h23) + 0.25f * __ldg(bb + gq);
            float4 vg = vv[gq];
            y0 = fmaf(s, vg.x, y0);
            y1 = fmaf(s, vg.y, y1);
            y2 = fmaf(s, vg.z, y2);
        }
    }

    // reduce over kq (lane bits 0-1)
    z0 += __shfl_xor_sync(0xffffffffu, z0, 1);
    y0 += __shfl_xor_sync(0xffffffffu, y0, 1);
    y1 += __shfl_xor_sync(0xffffffffu, y1, 1);
    y2 += __shfl_xor_sync(0xffffffffu, y2, 1);
    z0 += __shfl_xor_sync(0xffffffffu, z0, 2);
    y0 += __shfl_xor_sync(0xffffffffu, y0, 2);
    y1 += __shfl_xor_sync(0xffffffffu, y1, 2);
    y2 += __shfl_xor_sync(0xffffffffu, y2, 2);

    if (kq == 0) {
        msg[node * 64 + i] = z0;
        msg[node * 64 + 16 + i * 3 + 0] = y0;
        msg[node * 64 + 16 + i * 3 + 1] = y1;
        msg[node * 64 + 16 + i * 3 + 2] = y2;
    }
    __syncthreads();

    // ---- fused broadcast: 8 nodes -> 127 edges each ----
    const float4* mq = (const float4*)msg;
    const int bn0 = blk * NODES;
    int s12 = t % 12;
    int sb = s12 + 8; if (sb >= 12) sb -= 12;   // (t+512) % 12
    int sc = s12 + 4; if (sc >= 12) sc -= 12;   // (t+1024) % 12

    #pragma unroll 1
    for (int nn = 0; nn < NODES; nn++) {
        const float4* mrow = mq + nn * 16;      // [0..3]=msg0, [4..15]=msg1
        float4* o0 = out + (size_t)(bn0 + nn) * 508;
        if (t < 508) o0[t] = mrow[t & 3];
        float4* o1 = out + OUT1_BASE4 + (size_t)(bn0 + nn) * 1524;
        o1[t]       = mrow[4 + s12];
        o1[t + 512] = mrow[4 + sb];
        if (t < 500) o1[t + 1024] = mrow[4 + sc];
    }
}

extern "C" void kernel_launch(void* const* d_in, const int* in_sizes, int n_in,
                              void* d_out, int out_size)
{
    const float* r    = (const float*)d_in[0];
    const float* src0 = (const float*)d_in[1];
    const float* src1 = (const float*)d_in[2];
    const float* b00  = (const float*)d_in[3];
    const float* b01  = (const float*)d_in[4];
    const float* b10  = (const float*)d_in[5];
    const float* b11  = (const float*)d_in[6];
    const float* w1   = (const float*)d_in[7];
    const float* b1   = (const float*)d_in[8];
    const float* g1   = (const float*)d_in[9];
    const float* be1  = (const float*)d_in[10];
    const float* w2   = (const float*)d_in[11];
    const float* b2   = (const float*)d_in[12];
    const float* g2   = (const float*)d_in[13];
    const float* be2  = (const float*)d_in[14];
    const float* w300 = (const float*)d_in[15];
    const float* b300 = (const float*)d_in[16];
    const float* w301 = (const float*)d_in[17];
    const float* b301 = (const float*)d_in[18];
    const float* w310 = (const float*)d_in[19];
    const float* b310 = (const float*)d_in[20];
    const float* w311 = (const float*)d_in[21];
    const float* b311 = (const float*)d_in[22];

    fused_kernel<<<GROUPS, CT>>>(
        r, src0, src1, b00, b01, b10, b11,
        w1, b1, g1, be1, w2, b2, g2, be2,
        w300, b300, w301, b301, w310, b310, w311, b311,
        (float4*)d_out);
}